// round 2
// baseline (speedup 1.0000x reference)
#include <cuda_runtime.h>

#define NTOK 1032
#define EMB  768
#define NB   8
#define HEADS 12
#define HD   64
#define MTOT (NB * NTOK)   // 8256

// Scratch (allocation-free): kv activations and attention output
__device__ float g_kv[(size_t)MTOT * 2 * EMB];   // [m][0:768)=k, [768:1536)=v
__device__ float g_ao[(size_t)MTOT * EMB];

__device__ __forceinline__ float neg_inf() { return __int_as_float(0xff800000); }

// Gaussian attention bias: add[i][j] for the (PREFIX+DIM1*DIM2) token grid.
// exponent = -(c^2)((i1-j1)^2 + (i2-j2)^2), c^2 = 1/(2*std^2) = 0.02
__device__ __forceinline__ float gbias(int i, int j) {
    if (i < 8 || j < 8) return 0.0f;
    int p = i - 8, q = j - 8;
    int di = (p >> 5) - (q >> 5);
    int dl = (p & 31) - (q & 31);
    return __expf(-0.02f * (float)(di * di + dl * dl));
}

// ---------------------------------------------------------------------------
// C[M,N] = A[M,K] @ W[N,K]^T + bias[N]
// Tiles: BM=64, BN=128, BK=16; 256 threads; micro-tile 4x8 per thread.
// M % 64 == 0, N % 128 == 0, K % 16 == 0 guaranteed by problem shapes.
// ---------------------------------------------------------------------------
__global__ __launch_bounds__(256) void gemm_wt_bias(
    const float* __restrict__ A, const float* __restrict__ W,
    const float* __restrict__ bias, float* __restrict__ C,
    int M, int N, int K)
{
    __shared__ float As[16][64];
    __shared__ float Ws[16][128];

    const int tid = threadIdx.x;
    const int tx = tid & 15, ty = tid >> 4;
    const int m0 = blockIdx.y * 64, n0 = blockIdx.x * 128;

    float acc[4][8];
#pragma unroll
    for (int r = 0; r < 4; r++)
#pragma unroll
        for (int c = 0; c < 8; c++) acc[r][c] = 0.0f;

    const int lm = tid >> 2;          // 0..63
    const int lk = (tid & 3) << 2;    // 0,4,8,12
    const float* Ap  = A + (size_t)(m0 + lm) * K + lk;
    const float* Wp0 = W + (size_t)(n0 + lm) * K + lk;
    const float* Wp1 = Wp0 + (size_t)64 * K;

    for (int k0 = 0; k0 < K; k0 += 16) {
        float4 av = *(const float4*)(Ap + k0);
        float4 w0 = *(const float4*)(Wp0 + k0);
        float4 w1 = *(const float4*)(Wp1 + k0);
        As[lk + 0][lm] = av.x; As[lk + 1][lm] = av.y;
        As[lk + 2][lm] = av.z; As[lk + 3][lm] = av.w;
        Ws[lk + 0][lm] = w0.x; Ws[lk + 1][lm] = w0.y;
        Ws[lk + 2][lm] = w0.z; Ws[lk + 3][lm] = w0.w;
        Ws[lk + 0][lm + 64] = w1.x; Ws[lk + 1][lm + 64] = w1.y;
        Ws[lk + 2][lm + 64] = w1.z; Ws[lk + 3][lm + 64] = w1.w;
        __syncthreads();
#pragma unroll
        for (int k = 0; k < 16; k++) {
            float4 a4 = *(const float4*)&As[k][ty << 2];
            float4 b0 = *(const float4*)&Ws[k][tx << 3];
            float4 b1 = *(const float4*)&Ws[k][(tx << 3) + 4];
            float a[4]  = {a4.x, a4.y, a4.z, a4.w};
            float bv[8] = {b0.x, b0.y, b0.z, b0.w, b1.x, b1.y, b1.z, b1.w};
#pragma unroll
            for (int r = 0; r < 4; r++)
#pragma unroll
                for (int c = 0; c < 8; c++)
                    acc[r][c] = fmaf(a[r], bv[c], acc[r][c]);
        }
        __syncthreads();
    }

    const int cn = n0 + (tx << 3);
    float4 bb0 = *(const float4*)&bias[cn];
    float4 bb1 = *(const float4*)&bias[cn + 4];
#pragma unroll
    for (int r = 0; r < 4; r++) {
        float* Cp = C + (size_t)(m0 + (ty << 2) + r) * N + cn;
        float4 o0 = make_float4(acc[r][0] + bb0.x, acc[r][1] + bb0.y,
                                acc[r][2] + bb0.z, acc[r][3] + bb0.w);
        float4 o1 = make_float4(acc[r][4] + bb1.x, acc[r][5] + bb1.y,
                                acc[r][6] + bb1.z, acc[r][7] + bb1.w);
        *(float4*)Cp = o0;
        *(float4*)(Cp + 4) = o1;
    }
}

// ---------------------------------------------------------------------------
// Flash attention per (i-tile, head, batch):
//   S = Ki Kj^T * 0.125 + gauss_bias ; online softmax ; O += P Vj
// Tiles 64x64, hd=64. 256 threads, 4x4 micro-tile (thread (ty,tx)).
// smem: Ki[64][64] (i-rows x d), Kjt[64][64] (d x j, transposed; reused as
// P[64][64] i-rows x j for the PV GEMM), Vj[64][64] (j x d). 48 KB static.
// ---------------------------------------------------------------------------
__global__ __launch_bounds__(256) void attn_kernel(const float* __restrict__ kv,
                                                   float* __restrict__ out)
{
    __shared__ float Ki[64][64];
    __shared__ float KjtP[64][64];
    __shared__ float Vj[64][64];

    const int tid = threadIdx.x;
    const int tx = tid & 15, ty = tid >> 4;
    const int i0 = blockIdx.x * 64;
    const int h = blockIdx.y, b = blockIdx.z;

    const float* Kbase = kv + (size_t)b * NTOK * (2 * EMB) + h * HD;
    const float* Vbase = Kbase + EMB;

    const int lrow = tid >> 2;       // 0..63
    const int lq = tid & 3;          // 0..3

    // Load Ki (plain [row][d]); OOB rows -> 0
    {
        int gi = i0 + lrow;
        const float* src = Kbase + (size_t)gi * (2 * EMB);
#pragma unroll
        for (int qq = 0; qq < 4; qq++) {
            int u = lq + qq * 4;  // float4 unit 0..15
            float4 v = make_float4(0.f, 0.f, 0.f, 0.f);
            if (gi < NTOK) v = *(const float4*)(src + u * 4);
            *(float4*)&Ki[lrow][u * 4] = v;
        }
    }

    float m_[4], l_[4], o_[4][4];
#pragma unroll
    for (int r = 0; r < 4; r++) {
        m_[r] = neg_inf();
        l_[r] = 0.0f;
#pragma unroll
        for (int c = 0; c < 4; c++) o_[r][c] = 0.0f;
    }
    __syncthreads();

    const int njt = (NTOK + 63) / 64;   // 17
    for (int jt = 0; jt < njt; jt++) {
        const int j0 = jt * 64;
        // Load Kj transposed -> KjtP[d][j]; Vj plain [j][d]. OOB -> 0.
        {
            int gj = j0 + lrow;
            const float* ks = Kbase + (size_t)gj * (2 * EMB);
            const float* vs = Vbase + (size_t)gj * (2 * EMB);
#pragma unroll
            for (int qq = 0; qq < 4; qq++) {
                int u = lq + qq * 4;
                float4 kvv = make_float4(0.f, 0.f, 0.f, 0.f);
                float4 vvv = kvv;
                if (gj < NTOK) {
                    kvv = *(const float4*)(ks + u * 4);
                    vvv = *(const float4*)(vs + u * 4);
                }
                KjtP[u * 4 + 0][lrow] = kvv.x;
                KjtP[u * 4 + 1][lrow] = kvv.y;
                KjtP[u * 4 + 2][lrow] = kvv.z;
                KjtP[u * 4 + 3][lrow] = kvv.w;
                *(float4*)&Vj[lrow][u * 4] = vvv;
            }
        }
        __syncthreads();

        // S tile: s[r][c] = sum_d Ki[ty*4+r][d] * Kjt[d][tx*4+c]
        float s[4][4];
#pragma unroll
        for (int r = 0; r < 4; r++)
#pragma unroll
            for (int c = 0; c < 4; c++) s[r][c] = 0.0f;

#pragma unroll
        for (int d4 = 0; d4 < 16; d4++) {
            float a[4][4];
#pragma unroll
            for (int r = 0; r < 4; r++) {
                float4 a4 = *(const float4*)&Ki[ty * 4 + r][d4 * 4];
                a[r][0] = a4.x; a[r][1] = a4.y; a[r][2] = a4.z; a[r][3] = a4.w;
            }
#pragma unroll
            for (int dd = 0; dd < 4; dd++) {
                float4 b4 = *(const float4*)&KjtP[d4 * 4 + dd][tx * 4];
                float bv[4] = {b4.x, b4.y, b4.z, b4.w};
#pragma unroll
                for (int r = 0; r < 4; r++)
#pragma unroll
                    for (int c = 0; c < 4; c++)
                        s[r][c] = fmaf(a[r][dd], bv[c], s[r][c]);
            }
        }

        // Online softmax update (row stats across the 16 tx-threads of a row)
#pragma unroll
        for (int r = 0; r < 4; r++) {
            int gi = i0 + ty * 4 + r;
            float mx = neg_inf();
#pragma unroll
            for (int c = 0; c < 4; c++) {
                int gj = j0 + tx * 4 + c;
                float val = s[r][c] * 0.125f + gbias(gi, gj);
                val = (gj < NTOK) ? val : neg_inf();
                s[r][c] = val;
                mx = fmaxf(mx, val);
            }
#pragma unroll
            for (int off = 8; off > 0; off >>= 1)
                mx = fmaxf(mx, __shfl_xor_sync(0xffffffffu, mx, off));
            float mnew = fmaxf(m_[r], mx);
            float alpha = __expf(m_[r] - mnew);
            float rs = 0.0f;
#pragma unroll
            for (int c = 0; c < 4; c++) {
                float p = __expf(s[r][c] - mnew);
                s[r][c] = p;
                rs += p;
            }
#pragma unroll
            for (int off = 8; off > 0; off >>= 1)
                rs += __shfl_xor_sync(0xffffffffu, rs, off);
            m_[r] = mnew;
            l_[r] = l_[r] * alpha + rs;
#pragma unroll
            for (int c = 0; c < 4; c++) o_[r][c] *= alpha;
        }
        __syncthreads();   // all threads done reading KjtP as K^T

        // Write P tile (plain [i-row][j]) into the KjtP buffer
#pragma unroll
        for (int r = 0; r < 4; r++)
            *(float4*)&KjtP[ty * 4 + r][tx * 4] =
                make_float4(s[r][0], s[r][1], s[r][2], s[r][3]);
        __syncthreads();

        // O += P @ Vj  (O cols = tx*4..+3)
#pragma unroll 8
        for (int j = 0; j < 64; j++) {
            float4 vv = *(const float4*)&Vj[j][tx * 4];
#pragma unroll
            for (int r = 0; r < 4; r++) {
                float p = KjtP[ty * 4 + r][j];
                o_[r][0] = fmaf(p, vv.x, o_[r][0]);
                o_[r][1] = fmaf(p, vv.y, o_[r][1]);
                o_[r][2] = fmaf(p, vv.z, o_[r][2]);
                o_[r][3] = fmaf(p, vv.w, o_[r][3]);
            }
        }
        __syncthreads();   // before next tile overwrites KjtP / Vj
    }

    // Normalize and store: out[b, i, h*64 + col]
#pragma unroll
    for (int r = 0; r < 4; r++) {
        int gi = i0 + ty * 4 + r;
        if (gi < NTOK) {
            float inv = 1.0f / l_[r];
            float4 res = make_float4(o_[r][0] * inv, o_[r][1] * inv,
                                     o_[r][2] * inv, o_[r][3] * inv);
            *(float4*)&out[((size_t)b * NTOK + gi) * EMB + h * HD + tx * 4] = res;
        }
    }
}

// ---------------------------------------------------------------------------
extern "C" void kernel_launch(void* const* d_in, const int* in_sizes, int n_in,
                              void* d_out, int out_size)
{
    const float* x      = (const float*)d_in[0];
    const float* qkv_w  = (const float*)d_in[1];  // [2304, 768]
    const float* qkv_b  = (const float*)d_in[2];  // [2304]
    const float* proj_w = (const float*)d_in[3];  // [768, 768]
    const float* proj_b = (const float*)d_in[4];  // [768]
    float* out = (float*)d_out;

    float* kvp = nullptr;
    float* aop = nullptr;
    cudaGetSymbolAddress((void**)&kvp, g_kv);
    cudaGetSymbolAddress((void**)&aop, g_ao);

    // 1) kv = x @ qkv_w[768:2304].T + qkv_b[768:2304]   (q slice is unused!)
    gemm_wt_bias<<<dim3(1536 / 128, MTOT / 64), 256>>>(
        x, qkv_w + (size_t)768 * 768, qkv_b + 768, kvp, MTOT, 1536, 768);

    // 2) flash attention with analytic gaussian bias
    attn_kernel<<<dim3((NTOK + 63) / 64, HEADS, NB), 256>>>(kvp, aop);

    // 3) out = ao @ proj_w.T + proj_b
    gemm_wt_bias<<<dim3(768 / 128, MTOT / 64), 256>>>(
        aop, proj_w, proj_b, out, MTOT, 768, 768);
}

// round 3
// speedup vs baseline: 2.5368x; 2.5368x over previous
#include <cuda_runtime.h>
#include <math.h>

#define NTOK 1032
#define EMB  768
#define NB   8
#define HEADS 12
#define MTOT (NB * NTOK)   // 8256
#define NEGINF (-1e30f)

// Scratch (allocation-free)
__device__ float g_kv[(size_t)MTOT * 2 * EMB];   // [m][0:768)=k, [768:1536)=v
__device__ float g_ao[(size_t)MTOT * EMB];
__device__ float g_wtab[64];                     // w[u] = exp(-0.02 u^2)

__device__ __forceinline__ unsigned f2tf(float f) {
    unsigned r;
    asm("cvt.rna.tf32.f32 %0, %1;" : "=r"(r) : "f"(f));
    return r;
}

__device__ __forceinline__ void mma_tf32(float* c, const unsigned* a, unsigned b0, unsigned b1) {
    asm volatile(
        "mma.sync.aligned.m16n8k8.row.col.f32.tf32.tf32.f32 "
        "{%0,%1,%2,%3}, {%4,%5,%6,%7}, {%8,%9}, {%0,%1,%2,%3};"
        : "+f"(c[0]), "+f"(c[1]), "+f"(c[2]), "+f"(c[3])
        : "r"(a[0]), "r"(a[1]), "r"(a[2]), "r"(a[3]), "r"(b0), "r"(b1));
}

__global__ void init_wtab(float* w) {
    int t = threadIdx.x;
    if (t < 64) w[t] = __expf(-0.02f * (float)(t * t));
}

// ---------------------------------------------------------------------------
// C[M,N] = A[M,K] @ W[N,K]^T + bias[N]   (tf32 tensor-core)
// BM=64, BN=128, BK=32; 256 threads (8 warps, warp tile 32x32).
// M%64==0, N%128==0, K%32==0 guaranteed.
// ---------------------------------------------------------------------------
__global__ __launch_bounds__(256) void gemm_tf32(
    const float* __restrict__ A, const float* __restrict__ W,
    const float* __restrict__ bias, float* __restrict__ C,
    int M, int N, int K)
{
    __shared__ unsigned As[64][36];
    __shared__ unsigned Bs[128][36];

    const int tid = threadIdx.x;
    const int lane = tid & 31, wid = tid >> 5;
    const int g = lane >> 2, l = lane & 3;
    const int wm = (wid >> 2) * 32, wn = (wid & 3) * 32;
    const int m0 = blockIdx.y * 64, n0 = blockIdx.x * 128;

    float acc[2][4][4];
#pragma unroll
    for (int mt = 0; mt < 2; mt++)
#pragma unroll
        for (int nt = 0; nt < 4; nt++)
#pragma unroll
            for (int e = 0; e < 4; e++) acc[mt][nt][e] = 0.0f;

    const int NT = K / 32;
    // load mappings: A tile 64x32 -> 512 f4 (2/thread); B tile 128x32 -> 1024 f4 (4/thread)
    const int rA0 = tid >> 3, qA0 = tid & 7;        // + i*32 rows
    float4 ra[2], rb[4];

#define LOAD_TILE(KT)                                                          \
    {                                                                          \
        int kb = (KT) * 32;                                                    \
        _Pragma("unroll")                                                      \
        for (int i = 0; i < 2; i++)                                            \
            ra[i] = *(const float4*)(A + (size_t)(m0 + rA0 + i * 32) * K + kb + qA0 * 4); \
        _Pragma("unroll")                                                      \
        for (int i = 0; i < 4; i++)                                            \
            rb[i] = *(const float4*)(W + (size_t)(n0 + rA0 + i * 32) * K + kb + qA0 * 4); \
    }
#define STORE_TILE()                                                           \
    {                                                                          \
        _Pragma("unroll")                                                      \
        for (int i = 0; i < 2; i++) {                                          \
            unsigned* p = &As[rA0 + i * 32][qA0 * 4];                          \
            p[0] = f2tf(ra[i].x); p[1] = f2tf(ra[i].y);                        \
            p[2] = f2tf(ra[i].z); p[3] = f2tf(ra[i].w);                        \
        }                                                                      \
        _Pragma("unroll")                                                      \
        for (int i = 0; i < 4; i++) {                                          \
            unsigned* p = &Bs[rA0 + i * 32][qA0 * 4];                          \
            p[0] = f2tf(rb[i].x); p[1] = f2tf(rb[i].y);                        \
            p[2] = f2tf(rb[i].z); p[3] = f2tf(rb[i].w);                        \
        }                                                                      \
    }

    LOAD_TILE(0);
    STORE_TILE();
    __syncthreads();

    for (int kt = 0; kt < NT; kt++) {
        const bool more = (kt + 1) < NT;
        if (more) LOAD_TILE(kt + 1);

#pragma unroll
        for (int ks = 0; ks < 4; ks++) {
            int k0 = ks * 8;
            unsigned af[2][4], bf[4][2];
#pragma unroll
            for (int mt = 0; mt < 2; mt++) {
                int rr = wm + mt * 16 + g;
                af[mt][0] = As[rr][k0 + l];
                af[mt][1] = As[rr + 8][k0 + l];
                af[mt][2] = As[rr][k0 + 4 + l];
                af[mt][3] = As[rr + 8][k0 + 4 + l];
            }
#pragma unroll
            for (int nt = 0; nt < 4; nt++) {
                int cc = wn + nt * 8 + g;
                bf[nt][0] = Bs[cc][k0 + l];
                bf[nt][1] = Bs[cc][k0 + 4 + l];
            }
#pragma unroll
            for (int mt = 0; mt < 2; mt++)
#pragma unroll
                for (int nt = 0; nt < 4; nt++)
                    mma_tf32(acc[mt][nt], af[mt], bf[nt][0], bf[nt][1]);
        }
        __syncthreads();
        if (more) { STORE_TILE(); __syncthreads(); }
    }

    // epilogue
#pragma unroll
    for (int mt = 0; mt < 2; mt++) {
#pragma unroll
        for (int nt = 0; nt < 4; nt++) {
            int row = m0 + wm + mt * 16 + g;
            int col = n0 + wn + nt * 8 + (l << 1);
            float b0 = bias[col], b1 = bias[col + 1];
            *(float2*)&C[(size_t)row * N + col] =
                make_float2(acc[mt][nt][0] + b0, acc[mt][nt][1] + b1);
            *(float2*)&C[(size_t)(row + 8) * N + col] =
                make_float2(acc[mt][nt][2] + b0, acc[mt][nt][3] + b1);
        }
    }
#undef LOAD_TILE
#undef STORE_TILE
}

// ---------------------------------------------------------------------------
// Flash attention, tf32 tensor-core. Block = 128 thr (4 warps), i-tile 64.
// Warp w owns i-rows [w*16, w*16+16): softmax is warp-local.
// smem (XOR-swizzled, stride 64, 3 x 16KB = 48KB):
//   sA: Ki (A-frags hoisted to regs once) then reused as P tile
//   sK: Kj [j][d];  sV: V^T [d][j]
// ---------------------------------------------------------------------------
#define SW(r, c) ((((r) << 6)) + ((c) ^ (((r) & 7) << 2)))

__global__ __launch_bounds__(128) void attn_tf32(
    const float* __restrict__ kv, const float* __restrict__ wtab,
    float* __restrict__ out)
{
    __shared__ unsigned sA[64 * 64];
    __shared__ unsigned sK[64 * 64];
    __shared__ unsigned sV[64 * 64];

    const int tid = threadIdx.x, lane = tid & 31, w = tid >> 5;
    const int g = lane >> 2, l = lane & 3, l2 = l << 1;
    const int i0 = blockIdx.x * 64, h = blockIdx.y, b = blockIdx.z;

    const float* Kb = kv + (size_t)b * NTOK * (2 * EMB) + h * 64;
    const float* Vb = Kb + EMB;

    // ---- load Ki (rows 0..63 of i-tile) into sA, swizzled tf32 ----
    {
        int r = tid >> 1, gi = i0 + r;
        const float* src = Kb + (size_t)gi * (2 * EMB);
#pragma unroll
        for (int u = 0; u < 8; u++) {
            int q = ((tid & 1) << 3) + u;
            float4 vv = make_float4(0.f, 0.f, 0.f, 0.f);
            if (gi < NTOK) vv = *(const float4*)(src + q * 4);
            unsigned* p = &sA[SW(r, q * 4)];
            p[0] = f2tf(vv.x); p[1] = f2tf(vv.y); p[2] = f2tf(vv.z); p[3] = f2tf(vv.w);
        }
    }
    __syncthreads();

    // ---- hoist Ki A-fragments (warp-local rows) into registers ----
    unsigned ka[8][4];
    {
        int row = w * 16 + g;
#pragma unroll
        for (int ks = 0; ks < 8; ks++) {
            int k0 = ks * 8;
            ka[ks][0] = sA[SW(row, k0 + l)];
            ka[ks][1] = sA[SW(row + 8, k0 + l)];
            ka[ks][2] = sA[SW(row, k0 + 4 + l)];
            ka[ks][3] = sA[SW(row + 8, k0 + 4 + l)];
        }
    }

    float oacc[8][4];
#pragma unroll
    for (int nt = 0; nt < 8; nt++)
#pragma unroll
        for (int e = 0; e < 4; e++) oacc[nt][e] = 0.0f;
    float m0r = NEGINF, m1r = NEGINF, l0r = 0.0f, l1r = 0.0f;

    const int gi0 = i0 + w * 16 + g, gi1 = gi0 + 8;
    const int phi0 = (gi0 - 8) >> 5, plo0 = (gi0 - 8) & 31;
    const int phi1 = (gi1 - 8) >> 5, plo1 = (gi1 - 8) & 31;

    for (int jt = 0; jt < 17; jt++) {
        const int j0 = jt * 64;
        __syncthreads();   // previous iter's reads of sK/sV complete
        // ---- load Kj (swizzled [j][d]) and V^T (swizzled [d][j]) ----
        {
            int r = tid >> 1, gj = j0 + r;
            const float* ks = Kb + (size_t)gj * (2 * EMB);
            const float* vs = Vb + (size_t)gj * (2 * EMB);
#pragma unroll
            for (int u = 0; u < 8; u++) {
                int q = ((tid & 1) << 3) + u;
                float4 kk = make_float4(0.f, 0.f, 0.f, 0.f);
                float4 vv = kk;
                if (gj < NTOK) {
                    kk = *(const float4*)(ks + q * 4);
                    vv = *(const float4*)(vs + q * 4);
                }
                unsigned* p = &sK[SW(r, q * 4)];
                p[0] = f2tf(kk.x); p[1] = f2tf(kk.y); p[2] = f2tf(kk.z); p[3] = f2tf(kk.w);
                int d = q * 4;
                sV[SW(d + 0, r)] = f2tf(vv.x);
                sV[SW(d + 1, r)] = f2tf(vv.y);
                sV[SW(d + 2, r)] = f2tf(vv.z);
                sV[SW(d + 3, r)] = f2tf(vv.w);
            }
        }
        __syncthreads();

        // ---- S = Ki Kj^T ----
        float sacc[8][4];
#pragma unroll
        for (int nt = 0; nt < 8; nt++)
#pragma unroll
            for (int e = 0; e < 4; e++) sacc[nt][e] = 0.0f;
#pragma unroll
        for (int ks = 0; ks < 8; ks++) {
            int k0 = ks * 8;
#pragma unroll
            for (int nt = 0; nt < 8; nt++) {
                int jr = nt * 8 + g;
                unsigned b0 = sK[SW(jr, k0 + l)];
                unsigned b1 = sK[SW(jr, k0 + 4 + l)];
                mma_tf32(sacc[nt], ka[ks], b0, b1);
            }
        }

        // ---- bias + mask + online softmax (warp-local rows) ----
        float mx0 = NEGINF, mx1 = NEGINF;
#pragma unroll
        for (int nt = 0; nt < 8; nt++) {
#pragma unroll
            for (int e = 0; e < 2; e++) {
                int gj = j0 + nt * 8 + l2 + e;
                float bias0 = 0.0f, bias1 = 0.0f;
                if (gj >= 8) {
                    int qh = (gj - 8) >> 5, ql = (gj - 8) & 31;
                    if (gi0 >= 8)
                        bias0 = __ldg(&wtab[abs(phi0 - qh)]) * __ldg(&wtab[abs(plo0 - ql)]);
                    bias1 = __ldg(&wtab[abs(phi1 - qh)]) * __ldg(&wtab[abs(plo1 - ql)]);
                }
                float t0 = sacc[nt][e] * 0.125f + bias0;
                float t1 = sacc[nt][2 + e] * 0.125f + bias1;
                if (gj >= NTOK) { t0 = NEGINF; t1 = NEGINF; }
                sacc[nt][e] = t0;
                sacc[nt][2 + e] = t1;
                mx0 = fmaxf(mx0, t0);
                mx1 = fmaxf(mx1, t1);
            }
        }
        mx0 = fmaxf(mx0, __shfl_xor_sync(0xffffffffu, mx0, 1));
        mx0 = fmaxf(mx0, __shfl_xor_sync(0xffffffffu, mx0, 2));
        mx1 = fmaxf(mx1, __shfl_xor_sync(0xffffffffu, mx1, 1));
        mx1 = fmaxf(mx1, __shfl_xor_sync(0xffffffffu, mx1, 2));

        float mn0 = fmaxf(m0r, mx0), mn1 = fmaxf(m1r, mx1);
        float al0 = __expf(m0r - mn0), al1 = __expf(m1r - mn1);
        float s0 = 0.0f, s1 = 0.0f;

        int prow = w * 16 + g;
#pragma unroll
        for (int nt = 0; nt < 8; nt++) {
            int c = nt * 8 + l2;
            int a0i = SW(prow, c);
            int a1i = SW(prow + 8, c);
            float p00 = __expf(sacc[nt][0] - mn0);
            float p01 = __expf(sacc[nt][1] - mn0);
            float p10 = __expf(sacc[nt][2] - mn1);
            float p11 = __expf(sacc[nt][3] - mn1);
            s0 += p00 + p01;
            s1 += p10 + p11;
            sA[a0i] = f2tf(p00); sA[a0i + 1] = f2tf(p01);
            sA[a1i] = f2tf(p10); sA[a1i + 1] = f2tf(p11);
        }
        s0 += __shfl_xor_sync(0xffffffffu, s0, 1);
        s0 += __shfl_xor_sync(0xffffffffu, s0, 2);
        s1 += __shfl_xor_sync(0xffffffffu, s1, 1);
        s1 += __shfl_xor_sync(0xffffffffu, s1, 2);
        m0r = mn0; m1r = mn1;
        l0r = l0r * al0 + s0;
        l1r = l1r * al1 + s1;
#pragma unroll
        for (int nt = 0; nt < 8; nt++) {
            oacc[nt][0] *= al0; oacc[nt][1] *= al0;
            oacc[nt][2] *= al1; oacc[nt][3] *= al1;
        }
        __syncwarp();

        // ---- O += P @ Vj  (A = P rows warp-local, B = V^T) ----
#pragma unroll
        for (int ks = 0; ks < 8; ks++) {
            int k0 = ks * 8;
            unsigned af[4];
            af[0] = sA[SW(prow, k0 + l)];
            af[1] = sA[SW(prow + 8, k0 + l)];
            af[2] = sA[SW(prow, k0 + 4 + l)];
            af[3] = sA[SW(prow + 8, k0 + 4 + l)];
#pragma unroll
            for (int nt = 0; nt < 8; nt++) {
                int dr = nt * 8 + g;
                unsigned b0 = sV[SW(dr, k0 + l)];
                unsigned b1 = sV[SW(dr, k0 + 4 + l)];
                mma_tf32(oacc[nt], af, b0, b1);
            }
        }
        __syncwarp();   // P reads done before next-iter overwrite (warp-local)
    }

    // ---- epilogue ----
    float inv0 = 1.0f / l0r, inv1 = 1.0f / l1r;
#pragma unroll
    for (int nt = 0; nt < 8; nt++) {
        int d = h * 64 + nt * 8 + l2;
        if (gi0 < NTOK)
            *(float2*)&out[((size_t)b * NTOK + gi0) * EMB + d] =
                make_float2(oacc[nt][0] * inv0, oacc[nt][1] * inv0);
        if (gi1 < NTOK)
            *(float2*)&out[((size_t)b * NTOK + gi1) * EMB + d] =
                make_float2(oacc[nt][2] * inv1, oacc[nt][3] * inv1);
    }
}

// ---------------------------------------------------------------------------
extern "C" void kernel_launch(void* const* d_in, const int* in_sizes, int n_in,
                              void* d_out, int out_size)
{
    const float* x      = (const float*)d_in[0];
    const float* qkv_w  = (const float*)d_in[1];  // [2304, 768]
    const float* qkv_b  = (const float*)d_in[2];  // [2304]
    const float* proj_w = (const float*)d_in[3];  // [768, 768]
    const float* proj_b = (const float*)d_in[4];  // [768]
    float* out = (float*)d_out;

    float* kvp = nullptr;
    float* aop = nullptr;
    float* wtab = nullptr;
    cudaGetSymbolAddress((void**)&kvp, g_kv);
    cudaGetSymbolAddress((void**)&aop, g_ao);
    cudaGetSymbolAddress((void**)&wtab, g_wtab);

    init_wtab<<<1, 64>>>(wtab);

    // 1) kv = x @ qkv_w[768:2304].T + qkv_b[768:2304]   (q slice unused)
    gemm_tf32<<<dim3(1536 / 128, MTOT / 64), 256>>>(
        x, qkv_w + (size_t)768 * 768, qkv_b + 768, kvp, MTOT, 1536, 768);

    // 2) flash attention with analytic (separable) gaussian bias
    attn_tf32<<<dim3(17, HEADS, NB), 128>>>(kvp, wtab, aop);

    // 3) out = ao @ proj_w.T + proj_b
    gemm_tf32<<<dim3(768 / 128, MTOT / 64), 256>>>(
        aop, proj_w, proj_b, out, MTOT, 768, 768);
}

// round 7
// speedup vs baseline: 3.1109x; 1.2263x over previous
#include <cuda_runtime.h>
#include <math.h>

#define NTOK 1032
#define EMB  768
#define NB   8
#define HEADS 12
#define MTOT (NB * NTOK)   // 8256
#define KPAD 1152          // 9 i-tiles * 128 = 18 j-subtiles * 64
#define NEGINF (-1e30f)

// Scratch (allocation-free)
__device__ float g_kv[(size_t)MTOT * 2 * EMB];          // [m][0:768)=k, [768:1536)=v
__device__ float g_ao[(size_t)MTOT * EMB];
__device__ unsigned g_kt[(size_t)NB * HEADS * KPAD * 64];  // tf32 K [bh][tok][d]
__device__ unsigned g_vt[(size_t)NB * HEADS * 64 * KPAD];  // tf32 V^T [bh][d][tok]
__device__ float g_wtab[64];                             // w[u] = exp(-0.02 u^2)

__device__ __forceinline__ unsigned f2tf(float f) {
    unsigned r;
    asm("cvt.rna.tf32.f32 %0, %1;" : "=r"(r) : "f"(f));
    return r;
}

__device__ __forceinline__ void mma_tf32(float* c, const unsigned* a, unsigned b0, unsigned b1) {
    asm volatile(
        "mma.sync.aligned.m16n8k8.row.col.f32.tf32.tf32.f32 "
        "{%0,%1,%2,%3}, {%4,%5,%6,%7}, {%8,%9}, {%0,%1,%2,%3};"
        : "+f"(c[0]), "+f"(c[1]), "+f"(c[2]), "+f"(c[3])
        : "r"(a[0]), "r"(a[1]), "r"(a[2]), "r"(a[3]), "r"(b0), "r"(b1));
}

__global__ void init_wtab(float* w) {
    int t = threadIdx.x;
    if (t < 64) w[t] = __expf(-0.02f * (float)(t * t));
}

// ---------------------------------------------------------------------------
// C[M,N] = A[M,K] @ W[N,K]^T + bias[N]   (tf32 tensor-core)
// BM=64, BN=128, BK=32; 256 threads (8 warps, warp tile 32x32).
// ---------------------------------------------------------------------------
__global__ __launch_bounds__(256) void gemm_tf32(
    const float* __restrict__ A, const float* __restrict__ W,
    const float* __restrict__ bias, float* __restrict__ C,
    int M, int N, int K)
{
    __shared__ unsigned As[64][36];
    __shared__ unsigned Bs[128][36];

    const int tid = threadIdx.x;
    const int lane = tid & 31, wid = tid >> 5;
    const int g = lane >> 2, l = lane & 3;
    const int wm = (wid >> 2) * 32, wn = (wid & 3) * 32;
    const int m0 = blockIdx.y * 64, n0 = blockIdx.x * 128;

    float acc[2][4][4];
#pragma unroll
    for (int mt = 0; mt < 2; mt++)
#pragma unroll
        for (int nt = 0; nt < 4; nt++)
#pragma unroll
            for (int e = 0; e < 4; e++) acc[mt][nt][e] = 0.0f;

    const int NT = K / 32;
    const int rA0 = tid >> 3, qA0 = tid & 7;
    float4 ra[2], rb[4];

#define LOAD_TILE(KT)                                                          \
    {                                                                          \
        int kb = (KT) * 32;                                                    \
        _Pragma("unroll")                                                      \
        for (int i = 0; i < 2; i++)                                            \
            ra[i] = *(const float4*)(A + (size_t)(m0 + rA0 + i * 32) * K + kb + qA0 * 4); \
        _Pragma("unroll")                                                      \
        for (int i = 0; i < 4; i++)                                            \
            rb[i] = *(const float4*)(W + (size_t)(n0 + rA0 + i * 32) * K + kb + qA0 * 4); \
    }
#define STORE_TILE()                                                           \
    {                                                                          \
        _Pragma("unroll")                                                      \
        for (int i = 0; i < 2; i++) {                                          \
            unsigned* p = &As[rA0 + i * 32][qA0 * 4];                          \
            p[0] = f2tf(ra[i].x); p[1] = f2tf(ra[i].y);                        \
            p[2] = f2tf(ra[i].z); p[3] = f2tf(ra[i].w);                        \
        }                                                                      \
        _Pragma("unroll")                                                      \
        for (int i = 0; i < 4; i++) {                                          \
            unsigned* p = &Bs[rA0 + i * 32][qA0 * 4];                          \
            p[0] = f2tf(rb[i].x); p[1] = f2tf(rb[i].y);                        \
            p[2] = f2tf(rb[i].z); p[3] = f2tf(rb[i].w);                        \
        }                                                                      \
    }

    LOAD_TILE(0);
    STORE_TILE();
    __syncthreads();

    for (int kt = 0; kt < NT; kt++) {
        const bool more = (kt + 1) < NT;
        if (more) LOAD_TILE(kt + 1);

#pragma unroll
        for (int ks = 0; ks < 4; ks++) {
            int k0 = ks * 8;
            unsigned af[2][4], bf[4][2];
#pragma unroll
            for (int mt = 0; mt < 2; mt++) {
                int rr = wm + mt * 16 + g;
                af[mt][0] = As[rr][k0 + l];
                af[mt][1] = As[rr + 8][k0 + l];
                af[mt][2] = As[rr][k0 + 4 + l];
                af[mt][3] = As[rr + 8][k0 + 4 + l];
            }
#pragma unroll
            for (int nt = 0; nt < 4; nt++) {
                int cc = wn + nt * 8 + g;
                bf[nt][0] = Bs[cc][k0 + l];
                bf[nt][1] = Bs[cc][k0 + 4 + l];
            }
#pragma unroll
            for (int mt = 0; mt < 2; mt++)
#pragma unroll
                for (int nt = 0; nt < 4; nt++)
                    mma_tf32(acc[mt][nt], af[mt], bf[nt][0], bf[nt][1]);
        }
        __syncthreads();
        if (more) { STORE_TILE(); __syncthreads(); }
    }

#pragma unroll
    for (int mt = 0; mt < 2; mt++) {
#pragma unroll
        for (int nt = 0; nt < 4; nt++) {
            int row = m0 + wm + mt * 16 + g;
            int col = n0 + wn + nt * 8 + (l << 1);
            float b0 = bias[col], b1 = bias[col + 1];
            *(float2*)&C[(size_t)row * N + col] =
                make_float2(acc[mt][nt][0] + b0, acc[mt][nt][1] + b1);
            *(float2*)&C[(size_t)(row + 8) * N + col] =
                make_float2(acc[mt][nt][2] + b0, acc[mt][nt][3] + b1);
        }
    }
#undef LOAD_TILE
#undef STORE_TILE
}

// ---------------------------------------------------------------------------
// Repack: kv (f32) -> Kt tf32 [bh][KPAD][64] (zero-padded rows) and
//                     Vt tf32 [bh][64][KPAD] (transposed, zero-padded cols).
// Block = (jt, h, b), 256 threads, jt covers 64 tokens.
// ---------------------------------------------------------------------------
__global__ __launch_bounds__(256) void repack_kv(
    const float* __restrict__ kv, unsigned* __restrict__ Kt,
    unsigned* __restrict__ Vt)
{
    __shared__ float sv[64][65];
    const int tid = threadIdx.x;
    const int jt = blockIdx.x, h = blockIdx.y, b = blockIdx.z;
    const int j0 = jt * 64, bh = b * HEADS + h;

    const float* Kb = kv + (size_t)b * NTOK * (2 * EMB) + h * 64;
    const float* Vb = Kb + EMB;

#pragma unroll
    for (int i = 0; i < 4; i++) {
        int id = tid + i * 256;
        int r = id >> 4, q = (id & 15) << 2;   // row 0..63, col 0,4,..60
        int gj = j0 + r;
        float4 kk = make_float4(0.f, 0.f, 0.f, 0.f), vv = kk;
        if (gj < NTOK) {
            kk = *(const float4*)(Kb + (size_t)gj * (2 * EMB) + q);
            vv = *(const float4*)(Vb + (size_t)gj * (2 * EMB) + q);
        }
        uint4 ko = make_uint4(f2tf(kk.x), f2tf(kk.y), f2tf(kk.z), f2tf(kk.w));
        *(uint4*)&Kt[((size_t)bh * KPAD + j0 + r) * 64 + q] = ko;
        sv[r][q] = vv.x; sv[r][q + 1] = vv.y; sv[r][q + 2] = vv.z; sv[r][q + 3] = vv.w;
    }
    __syncthreads();

    const int d = tid >> 2, jb = (tid & 3) << 4;
#pragma unroll
    for (int c = 0; c < 4; c++) {
        int j = jb + c * 4;
        uint4 o = make_uint4(f2tf(sv[j][d]), f2tf(sv[j + 1][d]),
                             f2tf(sv[j + 2][d]), f2tf(sv[j + 3][d]));
        *(uint4*)&Vt[((size_t)bh * 64 + d) * KPAD + j0 + j] = o;
    }
}

// ---------------------------------------------------------------------------
// Flash attention, tf32 MMA. Block = 256 thr (8 warps), i-tile 128, j-tile 64.
// Warp w owns i-rows [w*16, w*16+16): softmax is warp-local.
// Dynamic smem: sK[64][68] (K tile [j][d]), sV[64][68] (V^T [d][j]),
//               sP[128][68] (P tile). 69632 B.
// ---------------------------------------------------------------------------
#define STR 68

extern __shared__ unsigned smem_dyn[];

__global__ __launch_bounds__(256) void attn_tf32(
    const unsigned* __restrict__ Kt, const unsigned* __restrict__ Vt,
    const float* __restrict__ wtab, float* __restrict__ out)
{
    unsigned* sK = smem_dyn;
    unsigned* sV = smem_dyn + 64 * STR;
    unsigned* sP = smem_dyn + 2 * 64 * STR;

    const int tid = threadIdx.x, lane = tid & 31, w = tid >> 5;
    const int g = lane >> 2, l = lane & 3, l2 = l << 1;
    const int i0 = blockIdx.x * 128, h = blockIdx.y, b = blockIdx.z;
    const int bh = b * HEADS + h;

    const unsigned* Ktb = Kt + (size_t)bh * KPAD * 64;
    const unsigned* Vtb = Vt + (size_t)bh * 64 * KPAD;

    // ---- hoist Ki A-fragments straight from global (padded -> no checks) ----
    const int r0 = i0 + w * 16 + g;
    unsigned ka[8][4];
#pragma unroll
    for (int ks = 0; ks < 8; ks++) {
        int k0 = ks * 8;
        ka[ks][0] = Ktb[(size_t)r0 * 64 + k0 + l];
        ka[ks][1] = Ktb[(size_t)(r0 + 8) * 64 + k0 + l];
        ka[ks][2] = Ktb[(size_t)r0 * 64 + k0 + 4 + l];
        ka[ks][3] = Ktb[(size_t)(r0 + 8) * 64 + k0 + 4 + l];
    }

    float oacc[8][4];
#pragma unroll
    for (int nt = 0; nt < 8; nt++)
#pragma unroll
        for (int e = 0; e < 4; e++) oacc[nt][e] = 0.0f;
    float m0r = NEGINF, m1r = NEGINF, l0r = 0.0f, l1r = 0.0f;

    const int gi0 = r0, gi1 = r0 + 8;
    const int phi0 = (gi0 - 8) >> 5, plo0 = (gi0 - 8) & 31;
    const int phi1 = (gi1 - 8) >> 5, plo1 = (gi1 - 8) & 31;
    const int prow = w * 16 + g;

    for (int jt = 0; jt < 17; jt++) {
        const int j0 = jt * 64;
        if (jt) __syncthreads();   // prior iter's sK/sV reads complete

        // ---- stage K tile [j][d] and V^T tile [d][j]: pure LDG.128/STS.128 ----
#pragma unroll
        for (int i = 0; i < 4; i++) {
            int id = tid + i * 256;
            int r = id >> 4, q = (id & 15) << 2;
            uint4 kk = *(const uint4*)&Ktb[((size_t)(j0 + r)) * 64 + q];
            uint4 vv = *(const uint4*)&Vtb[(size_t)r * KPAD + j0 + q];
            *(uint4*)&sK[r * STR + q] = kk;
            *(uint4*)&sV[r * STR + q] = vv;
        }
        __syncthreads();

        // ---- S = Ki Kj^T ----
        float sacc[8][4];
#pragma unroll
        for (int nt = 0; nt < 8; nt++)
#pragma unroll
            for (int e = 0; e < 4; e++) sacc[nt][e] = 0.0f;
#pragma unroll
        for (int ks = 0; ks < 8; ks++) {
            int k0 = ks * 8;
#pragma unroll
            for (int nt = 0; nt < 8; nt++) {
                int jr = nt * 8 + g;
                unsigned b0 = sK[jr * STR + k0 + l];
                unsigned b1 = sK[jr * STR + k0 + 4 + l];
                mma_tf32(sacc[nt], ka[ks], b0, b1);
            }
        }

        // ---- bias + mask + online softmax (warp-local rows) ----
        float mx0 = NEGINF, mx1 = NEGINF;
#pragma unroll
        for (int nt = 0; nt < 8; nt++) {
#pragma unroll
            for (int e = 0; e < 2; e++) {
                int gj = j0 + nt * 8 + l2 + e;
                float bias0 = 0.0f, bias1 = 0.0f;
                if (gj >= 8) {
                    int qh = (gj - 8) >> 5, ql = (gj - 8) & 31;
                    if (gi0 >= 8)
                        bias0 = __ldg(&wtab[abs(phi0 - qh)]) * __ldg(&wtab[abs(plo0 - ql)]);
                    bias1 = __ldg(&wtab[abs(phi1 - qh)]) * __ldg(&wtab[abs(plo1 - ql)]);
                }
                float t0 = sacc[nt][e] * 0.125f + bias0;
                float t1 = sacc[nt][2 + e] * 0.125f + bias1;
                if (gj >= NTOK) { t0 = NEGINF; t1 = NEGINF; }
                sacc[nt][e] = t0;
                sacc[nt][2 + e] = t1;
                mx0 = fmaxf(mx0, t0);
                mx1 = fmaxf(mx1, t1);
            }
        }
        mx0 = fmaxf(mx0, __shfl_xor_sync(0xffffffffu, mx0, 1));
        mx0 = fmaxf(mx0, __shfl_xor_sync(0xffffffffu, mx0, 2));
        mx1 = fmaxf(mx1, __shfl_xor_sync(0xffffffffu, mx1, 1));
        mx1 = fmaxf(mx1, __shfl_xor_sync(0xffffffffu, mx1, 2));

        float mn0 = fmaxf(m0r, mx0), mn1 = fmaxf(m1r, mx1);
        float al0 = __expf(m0r - mn0), al1 = __expf(m1r - mn1);
        float s0 = 0.0f, s1 = 0.0f;

#pragma unroll
        for (int nt = 0; nt < 8; nt++) {
            int c = nt * 8 + l2;
            float p00 = __expf(sacc[nt][0] - mn0);
            float p01 = __expf(sacc[nt][1] - mn0);
            float p10 = __expf(sacc[nt][2] - mn1);
            float p11 = __expf(sacc[nt][3] - mn1);
            s0 += p00 + p01;
            s1 += p10 + p11;
            sP[prow * STR + c] = f2tf(p00);
            sP[prow * STR + c + 1] = f2tf(p01);
            sP[(prow + 8) * STR + c] = f2tf(p10);
            sP[(prow + 8) * STR + c + 1] = f2tf(p11);
        }
        s0 += __shfl_xor_sync(0xffffffffu, s0, 1);
        s0 += __shfl_xor_sync(0xffffffffu, s0, 2);
        s1 += __shfl_xor_sync(0xffffffffu, s1, 1);
        s1 += __shfl_xor_sync(0xffffffffu, s1, 2);
        m0r = mn0; m1r = mn1;
        l0r = l0r * al0 + s0;
        l1r = l1r * al1 + s1;
#pragma unroll
        for (int nt = 0; nt < 8; nt++) {
            oacc[nt][0] *= al0; oacc[nt][1] *= al0;
            oacc[nt][2] *= al1; oacc[nt][3] *= al1;
        }
        __syncwarp();   // P stores visible to this warp's MMA reads

        // ---- O += P @ Vj : A = P (warp-local rows), B = V^T ----
#pragma unroll
        for (int ks = 0; ks < 8; ks++) {
            int k0 = ks * 8;
            unsigned af[4];
            af[0] = sP[prow * STR + k0 + l];
            af[1] = sP[(prow + 8) * STR + k0 + l];
            af[2] = sP[prow * STR + k0 + 4 + l];
            af[3] = sP[(prow + 8) * STR + k0 + 4 + l];
#pragma unroll
            for (int nt = 0; nt < 8; nt++) {
                int dr = nt * 8 + g;
                unsigned b0 = sV[dr * STR + k0 + l];
                unsigned b1 = sV[dr * STR + k0 + 4 + l];
                mma_tf32(oacc[nt], af, b0, b1);
            }
        }
        __syncwarp();
    }

    // ---- epilogue ----
    float inv0 = 1.0f / l0r, inv1 = 1.0f / l1r;
#pragma unroll
    for (int nt = 0; nt < 8; nt++) {
        int d = h * 64 + nt * 8 + l2;
        if (gi0 < NTOK)
            *(float2*)&out[((size_t)b * NTOK + gi0) * EMB + d] =
                make_float2(oacc[nt][0] * inv0, oacc[nt][1] * inv0);
        if (gi1 < NTOK)
            *(float2*)&out[((size_t)b * NTOK + gi1) * EMB + d] =
                make_float2(oacc[nt][2] * inv1, oacc[nt][3] * inv1);
    }
}

// ---------------------------------------------------------------------------
extern "C" void kernel_launch(void* const* d_in, const int* in_sizes, int n_in,
                              void* d_out, int out_size)
{
    const float* x      = (const float*)d_in[0];
    const float* qkv_w  = (const float*)d_in[1];  // [2304, 768]
    const float* qkv_b  = (const float*)d_in[2];  // [2304]
    const float* proj_w = (const float*)d_in[3];  // [768, 768]
    const float* proj_b = (const float*)d_in[4];  // [768]
    float* out = (float*)d_out;

    float *kvp = nullptr, *aop = nullptr, *wtab = nullptr;
    unsigned *ktp = nullptr, *vtp = nullptr;
    cudaGetSymbolAddress((void**)&kvp, g_kv);
    cudaGetSymbolAddress((void**)&aop, g_ao);
    cudaGetSymbolAddress((void**)&wtab, g_wtab);
    cudaGetSymbolAddress((void**)&ktp, g_kt);
    cudaGetSymbolAddress((void**)&vtp, g_vt);

    static bool attr_set = false;
    if (!attr_set) {
        cudaFuncSetAttribute(attn_tf32, cudaFuncAttributeMaxDynamicSharedMemorySize,
                             (2 * 64 * STR + 128 * STR) * 4);
        attr_set = true;
    }

    init_wtab<<<1, 64>>>(wtab);

    // 1) kv = x @ qkv_w[768:2304].T + qkv_b[768:2304]   (q slice unused)
    gemm_tf32<<<dim3(1536 / 128, MTOT / 64), 256>>>(
        x, qkv_w + (size_t)768 * 768, qkv_b + 768, kvp, MTOT, 1536, 768);

    // 2) repack to tf32: K [bh][tok][d] zero-padded, V^T [bh][d][tok]
    repack_kv<<<dim3(KPAD / 64, HEADS, NB), 256>>>(kvp, ktp, vtp);

    // 3) flash attention
    attn_tf32<<<dim3(KPAD / 128, HEADS, NB), 256, (2 * 64 * STR + 128 * STR) * 4>>>(
        ktp, vtp, wtab, aop);

    // 4) out = ao @ proj_w.T + proj_b
    gemm_tf32<<<dim3(768 / 128, MTOT / 64), 256>>>(
        aop, proj_w, proj_b, out, MTOT, 768, 768);
}

// round 8
// speedup vs baseline: 3.2042x; 1.0300x over previous
#include <cuda_runtime.h>
#include <math.h>

#define NTOK 1032
#define EMB  768
#define NB   8
#define HEADS 12
#define MTOT (NB * NTOK)   // 8256
#define KPAD 1152          // 9 i-tiles * 128 = 18 j-subtiles * 64
#define NEGINF (-1e30f)

// Scratch (allocation-free)
__device__ float g_kv[(size_t)MTOT * 2 * EMB];          // [m][0:768)=k, [768:1536)=v
__device__ float g_ao[(size_t)MTOT * EMB];
__device__ unsigned g_kt[(size_t)NB * HEADS * KPAD * 64];  // tf32 K [bh][tok][d]
__device__ unsigned g_vt[(size_t)NB * HEADS * 64 * KPAD];  // tf32 V^T [bh][d][tok]
__device__ float g_wtab[64];                             // w[u] = exp(-0.02 u^2)

__device__ __forceinline__ unsigned f2tf(float f) {
    unsigned r;
    asm("cvt.rna.tf32.f32 %0, %1;" : "=r"(r) : "f"(f));
    return r;
}

__device__ __forceinline__ void mma_tf32(float* c, const unsigned* a, unsigned b0, unsigned b1) {
    asm volatile(
        "mma.sync.aligned.m16n8k8.row.col.f32.tf32.tf32.f32 "
        "{%0,%1,%2,%3}, {%4,%5,%6,%7}, {%8,%9}, {%0,%1,%2,%3};"
        : "+f"(c[0]), "+f"(c[1]), "+f"(c[2]), "+f"(c[3])
        : "r"(a[0]), "r"(a[1]), "r"(a[2]), "r"(a[3]), "r"(b0), "r"(b1));
}

__device__ __forceinline__ void cp_async16(void* smem_dst, const void* gmem_src) {
    unsigned d = (unsigned)__cvta_generic_to_shared(smem_dst);
    asm volatile("cp.async.cg.shared.global [%0], [%1], 16;" :: "r"(d), "l"(gmem_src));
}
__device__ __forceinline__ void cp_commit() {
    asm volatile("cp.async.commit_group;");
}
__device__ __forceinline__ void cp_wait1() {
    asm volatile("cp.async.wait_group 1;");
}

__global__ void init_wtab(float* w) {
    int t = threadIdx.x;
    if (t < 64) w[t] = __expf(-0.02f * (float)(t * t));
}

// ---------------------------------------------------------------------------
// C[M,N] = A[M,K] @ W[N,K]^T + bias[N]   (tf32 tensor-core)
// BM=64, BN=128, BK=32; 256 threads (8 warps, warp tile 32x32).
// ---------------------------------------------------------------------------
__global__ __launch_bounds__(256) void gemm_tf32(
    const float* __restrict__ A, const float* __restrict__ W,
    const float* __restrict__ bias, float* __restrict__ C,
    int M, int N, int K)
{
    __shared__ unsigned As[64][36];
    __shared__ unsigned Bs[128][36];

    const int tid = threadIdx.x;
    const int lane = tid & 31, wid = tid >> 5;
    const int g = lane >> 2, l = lane & 3;
    const int wm = (wid >> 2) * 32, wn = (wid & 3) * 32;
    const int m0 = blockIdx.y * 64, n0 = blockIdx.x * 128;

    float acc[2][4][4];
#pragma unroll
    for (int mt = 0; mt < 2; mt++)
#pragma unroll
        for (int nt = 0; nt < 4; nt++)
#pragma unroll
            for (int e = 0; e < 4; e++) acc[mt][nt][e] = 0.0f;

    const int NT = K / 32;
    const int rA0 = tid >> 3, qA0 = tid & 7;
    float4 ra[2], rb[4];

#define LOAD_TILE(KT)                                                          \
    {                                                                          \
        int kb = (KT) * 32;                                                    \
        _Pragma("unroll")                                                      \
        for (int i = 0; i < 2; i++)                                            \
            ra[i] = *(const float4*)(A + (size_t)(m0 + rA0 + i * 32) * K + kb + qA0 * 4); \
        _Pragma("unroll")                                                      \
        for (int i = 0; i < 4; i++)                                            \
            rb[i] = *(const float4*)(W + (size_t)(n0 + rA0 + i * 32) * K + kb + qA0 * 4); \
    }
#define STORE_TILE()                                                           \
    {                                                                          \
        _Pragma("unroll")                                                      \
        for (int i = 0; i < 2; i++) {                                          \
            unsigned* p = &As[rA0 + i * 32][qA0 * 4];                          \
            p[0] = f2tf(ra[i].x); p[1] = f2tf(ra[i].y);                        \
            p[2] = f2tf(ra[i].z); p[3] = f2tf(ra[i].w);                        \
        }                                                                      \
        _Pragma("unroll")                                                      \
        for (int i = 0; i < 4; i++) {                                          \
            unsigned* p = &Bs[rA0 + i * 32][qA0 * 4];                          \
            p[0] = f2tf(rb[i].x); p[1] = f2tf(rb[i].y);                        \
            p[2] = f2tf(rb[i].z); p[3] = f2tf(rb[i].w);                        \
        }                                                                      \
    }

    LOAD_TILE(0);
    STORE_TILE();
    __syncthreads();

    for (int kt = 0; kt < NT; kt++) {
        const bool more = (kt + 1) < NT;
        if (more) LOAD_TILE(kt + 1);

#pragma unroll
        for (int ks = 0; ks < 4; ks++) {
            int k0 = ks * 8;
            unsigned af[2][4], bf[4][2];
#pragma unroll
            for (int mt = 0; mt < 2; mt++) {
                int rr = wm + mt * 16 + g;
                af[mt][0] = As[rr][k0 + l];
                af[mt][1] = As[rr + 8][k0 + l];
                af[mt][2] = As[rr][k0 + 4 + l];
                af[mt][3] = As[rr + 8][k0 + 4 + l];
            }
#pragma unroll
            for (int nt = 0; nt < 4; nt++) {
                int cc = wn + nt * 8 + g;
                bf[nt][0] = Bs[cc][k0 + l];
                bf[nt][1] = Bs[cc][k0 + 4 + l];
            }
#pragma unroll
            for (int mt = 0; mt < 2; mt++)
#pragma unroll
                for (int nt = 0; nt < 4; nt++)
                    mma_tf32(acc[mt][nt], af[mt], bf[nt][0], bf[nt][1]);
        }
        __syncthreads();
        if (more) { STORE_TILE(); __syncthreads(); }
    }

#pragma unroll
    for (int mt = 0; mt < 2; mt++) {
#pragma unroll
        for (int nt = 0; nt < 4; nt++) {
            int row = m0 + wm + mt * 16 + g;
            int col = n0 + wn + nt * 8 + (l << 1);
            float b0 = bias[col], b1 = bias[col + 1];
            *(float2*)&C[(size_t)row * N + col] =
                make_float2(acc[mt][nt][0] + b0, acc[mt][nt][1] + b1);
            *(float2*)&C[(size_t)(row + 8) * N + col] =
                make_float2(acc[mt][nt][2] + b0, acc[mt][nt][3] + b1);
        }
    }
#undef LOAD_TILE
#undef STORE_TILE
}

// ---------------------------------------------------------------------------
// Repack: kv (f32) -> Kt tf32 [bh][KPAD][64] (zero-padded rows) and
//                     Vt tf32 [bh][64][KPAD] (transposed, zero-padded cols).
// ---------------------------------------------------------------------------
__global__ __launch_bounds__(256) void repack_kv(
    const float* __restrict__ kv, unsigned* __restrict__ Kt,
    unsigned* __restrict__ Vt)
{
    __shared__ float sv[64][65];
    const int tid = threadIdx.x;
    const int jt = blockIdx.x, h = blockIdx.y, b = blockIdx.z;
    const int j0 = jt * 64, bh = b * HEADS + h;

    const float* Kb = kv + (size_t)b * NTOK * (2 * EMB) + h * 64;
    const float* Vb = Kb + EMB;

#pragma unroll
    for (int i = 0; i < 4; i++) {
        int id = tid + i * 256;
        int r = id >> 4, q = (id & 15) << 2;   // row 0..63, col 0,4,..60
        int gj = j0 + r;
        float4 kk = make_float4(0.f, 0.f, 0.f, 0.f), vv = kk;
        if (gj < NTOK) {
            kk = *(const float4*)(Kb + (size_t)gj * (2 * EMB) + q);
            vv = *(const float4*)(Vb + (size_t)gj * (2 * EMB) + q);
        }
        uint4 ko = make_uint4(f2tf(kk.x), f2tf(kk.y), f2tf(kk.z), f2tf(kk.w));
        *(uint4*)&Kt[((size_t)bh * KPAD + j0 + r) * 64 + q] = ko;
        sv[r][q] = vv.x; sv[r][q + 1] = vv.y; sv[r][q + 2] = vv.z; sv[r][q + 3] = vv.w;
    }
    __syncthreads();

    const int d = tid >> 2, jb = (tid & 3) << 4;
#pragma unroll
    for (int c = 0; c < 4; c++) {
        int j = jb + c * 4;
        uint4 o = make_uint4(f2tf(sv[j][d]), f2tf(sv[j + 1][d]),
                             f2tf(sv[j + 2][d]), f2tf(sv[j + 3][d]));
        *(uint4*)&Vt[((size_t)bh * 64 + d) * KPAD + j0 + j] = o;
    }
}

// ---------------------------------------------------------------------------
// Flash attention, tf32 MMA. Block = 256 thr (8 warps), i-tile 128, j-tile 64.
// Warp w owns i-rows [w*16, w*16+16): softmax is warp-local.
// Dynamic smem (104448 B):
//   sK[2][64][68]  K tile ring   (cp.async double buffered)
//   sV[2][64][68]  V^T tile ring (cp.async double buffered)
//   sP[128][68]    P tile
// Per j-tile: issue cp.async for tile jt+1, wait_group 1 (tile jt complete,
// tile jt+1 in flight), compute tile jt. Staging latency fully overlapped.
// ---------------------------------------------------------------------------
#define STR 68
#define TBUF (64 * STR)

extern __shared__ unsigned smem_dyn[];

__global__ __launch_bounds__(256) void attn_tf32(
    const unsigned* __restrict__ Kt, const unsigned* __restrict__ Vt,
    const float* __restrict__ wtab, float* __restrict__ out)
{
    unsigned* sK = smem_dyn;                   // 2 * TBUF
    unsigned* sV = smem_dyn + 2 * TBUF;        // 2 * TBUF
    unsigned* sP = smem_dyn + 4 * TBUF;        // 128 * STR

    const int tid = threadIdx.x, lane = tid & 31, w = tid >> 5;
    const int g = lane >> 2, l = lane & 3, l2 = l << 1;
    const int i0 = blockIdx.x * 128, h = blockIdx.y, b = blockIdx.z;
    const int bh = b * HEADS + h;

    const unsigned* Ktb = Kt + (size_t)bh * KPAD * 64;
    const unsigned* Vtb = Vt + (size_t)bh * 64 * KPAD;

    // per-thread staging coordinates (4 x (16B K + 16B V) per thread per tile)
    const int srow = tid >> 4;            // 0..15 (+16 per i)
    const int scol = (tid & 15) << 2;     // 0,4,..60

    auto stage = [&](int jt, int buf) {
        const int j0 = jt * 64;
        unsigned* sKb = sK + buf * TBUF;
        unsigned* sVb = sV + buf * TBUF;
#pragma unroll
        for (int i = 0; i < 4; i++) {
            int r = srow + i * 16;
            cp_async16(&sKb[r * STR + scol], &Ktb[(size_t)(j0 + r) * 64 + scol]);
            cp_async16(&sVb[r * STR + scol], &Vtb[(size_t)r * KPAD + j0 + scol]);
        }
    };

    // ---- hoist Ki A-fragments straight from global (padded -> no checks) ----
    const int r0 = i0 + w * 16 + g;
    unsigned ka[8][4];
#pragma unroll
    for (int ks = 0; ks < 8; ks++) {
        int k0 = ks * 8;
        ka[ks][0] = Ktb[(size_t)r0 * 64 + k0 + l];
        ka[ks][1] = Ktb[(size_t)(r0 + 8) * 64 + k0 + l];
        ka[ks][2] = Ktb[(size_t)r0 * 64 + k0 + 4 + l];
        ka[ks][3] = Ktb[(size_t)(r0 + 8) * 64 + k0 + 4 + l];
    }

    float oacc[8][4];
#pragma unroll
    for (int nt = 0; nt < 8; nt++)
#pragma unroll
        for (int e = 0; e < 4; e++) oacc[nt][e] = 0.0f;
    float m0r = NEGINF, m1r = NEGINF, l0r = 0.0f, l1r = 0.0f;

    const int gi0 = r0, gi1 = r0 + 8;
    const int phi0 = (gi0 - 8) >> 5, plo0 = (gi0 - 8) & 31;
    const int phi1 = (gi1 - 8) >> 5, plo1 = (gi1 - 8) & 31;
    const int prow = w * 16 + g;

    // prologue: stage tile 0 (group 0)
    stage(0, 0);
    cp_commit();

    for (int jt = 0; jt < 17; jt++) {
        const int j0 = jt * 64;
        const int buf = jt & 1;

        // issue next tile's copies (kept in flight during this tile's compute)
        if (jt < 16) stage(jt + 1, buf ^ 1);
        cp_commit();            // empty group on last iter keeps count aligned
        cp_wait1();             // tile jt complete; tile jt+1 may still fly
        __syncthreads();        // all threads' copies visible

        const unsigned* sKb = sK + buf * TBUF;
        const unsigned* sVb = sV + buf * TBUF;

        // ---- S = Ki Kj^T ----
        float sacc[8][4];
#pragma unroll
        for (int nt = 0; nt < 8; nt++)
#pragma unroll
            for (int e = 0; e < 4; e++) sacc[nt][e] = 0.0f;
#pragma unroll
        for (int ks = 0; ks < 8; ks++) {
            int k0 = ks * 8;
#pragma unroll
            for (int nt = 0; nt < 8; nt++) {
                int jr = nt * 8 + g;
                unsigned b0 = sKb[jr * STR + k0 + l];
                unsigned b1 = sKb[jr * STR + k0 + 4 + l];
                mma_tf32(sacc[nt], ka[ks], b0, b1);
            }
        }

        // ---- bias + mask + online softmax (warp-local rows) ----
        float mx0 = NEGINF, mx1 = NEGINF;
#pragma unroll
        for (int nt = 0; nt < 8; nt++) {
#pragma unroll
            for (int e = 0; e < 2; e++) {
                int gj = j0 + nt * 8 + l2 + e;
                float bias0 = 0.0f, bias1 = 0.0f;
                if (gj >= 8) {
                    int qh = (gj - 8) >> 5, ql = (gj - 8) & 31;
                    if (gi0 >= 8)
                        bias0 = __ldg(&wtab[abs(phi0 - qh)]) * __ldg(&wtab[abs(plo0 - ql)]);
                    bias1 = __ldg(&wtab[abs(phi1 - qh)]) * __ldg(&wtab[abs(plo1 - ql)]);
                }
                float t0 = sacc[nt][e] * 0.125f + bias0;
                float t1 = sacc[nt][2 + e] * 0.125f + bias1;
                if (gj >= NTOK) { t0 = NEGINF; t1 = NEGINF; }
                sacc[nt][e] = t0;
                sacc[nt][2 + e] = t1;
                mx0 = fmaxf(mx0, t0);
                mx1 = fmaxf(mx1, t1);
            }
        }
        mx0 = fmaxf(mx0, __shfl_xor_sync(0xffffffffu, mx0, 1));
        mx0 = fmaxf(mx0, __shfl_xor_sync(0xffffffffu, mx0, 2));
        mx1 = fmaxf(mx1, __shfl_xor_sync(0xffffffffu, mx1, 1));
        mx1 = fmaxf(mx1, __shfl_xor_sync(0xffffffffu, mx1, 2));

        float mn0 = fmaxf(m0r, mx0), mn1 = fmaxf(m1r, mx1);
        float al0 = __expf(m0r - mn0), al1 = __expf(m1r - mn1);
        float s0 = 0.0f, s1 = 0.0f;

#pragma unroll
        for (int nt = 0; nt < 8; nt++) {
            int c = nt * 8 + l2;
            float p00 = __expf(sacc[nt][0] - mn0);
            float p01 = __expf(sacc[nt][1] - mn0);
            float p10 = __expf(sacc[nt][2] - mn1);
            float p11 = __expf(sacc[nt][3] - mn1);
            s0 += p00 + p01;
            s1 += p10 + p11;
            sP[prow * STR + c] = f2tf(p00);
            sP[prow * STR + c + 1] = f2tf(p01);
            sP[(prow + 8) * STR + c] = f2tf(p10);
            sP[(prow + 8) * STR + c + 1] = f2tf(p11);
        }
        s0 += __shfl_xor_sync(0xffffffffu, s0, 1);
        s0 += __shfl_xor_sync(0xffffffffu, s0, 2);
        s1 += __shfl_xor_sync(0xffffffffu, s1, 1);
        s1 += __shfl_xor_sync(0xffffffffu, s1, 2);
        m0r = mn0; m1r = mn1;
        l0r = l0r * al0 + s0;
        l1r = l1r * al1 + s1;
#pragma unroll
        for (int nt = 0; nt < 8; nt++) {
            oacc[nt][0] *= al0; oacc[nt][1] *= al0;
            oacc[nt][2] *= al1; oacc[nt][3] *= al1;
        }
        __syncwarp();   // P stores visible to this warp's MMA reads

        // ---- O += P @ Vj : A = P (warp-local rows), B = V^T ----
#pragma unroll
        for (int ks = 0; ks < 8; ks++) {
            int k0 = ks * 8;
            unsigned af[4];
            af[0] = sP[prow * STR + k0 + l];
            af[1] = sP[(prow + 8) * STR + k0 + l];
            af[2] = sP[prow * STR + k0 + 4 + l];
            af[3] = sP[(prow + 8) * STR + k0 + 4 + l];
#pragma unroll
            for (int nt = 0; nt < 8; nt++) {
                int dr = nt * 8 + g;
                unsigned b0 = sVb[dr * STR + k0 + l];
                unsigned b1 = sVb[dr * STR + k0 + 4 + l];
                mma_tf32(oacc[nt], af, b0, b1);
            }
        }
        __syncthreads();  // all reads of this buf done before it is re-staged
    }

    // ---- epilogue ----
    float inv0 = 1.0f / l0r, inv1 = 1.0f / l1r;
#pragma unroll
    for (int nt = 0; nt < 8; nt++) {
        int d = h * 64 + nt * 8 + l2;
        if (gi0 < NTOK)
            *(float2*)&out[((size_t)b * NTOK + gi0) * EMB + d] =
                make_float2(oacc[nt][0] * inv0, oacc[nt][1] * inv0);
        if (gi1 < NTOK)
            *(float2*)&out[((size_t)b * NTOK + gi1) * EMB + d] =
                make_float2(oacc[nt][2] * inv1, oacc[nt][3] * inv1);
    }
}

// ---------------------------------------------------------------------------
extern "C" void kernel_launch(void* const* d_in, const int* in_sizes, int n_in,
                              void* d_out, int out_size)
{
    const float* x      = (const float*)d_in[0];
    const float* qkv_w  = (const float*)d_in[1];  // [2304, 768]
    const float* qkv_b  = (const float*)d_in[2];  // [2304]
    const float* proj_w = (const float*)d_in[3];  // [768, 768]
    const float* proj_b = (const float*)d_in[4];  // [768]
    float* out = (float*)d_out;

    float *kvp = nullptr, *aop = nullptr, *wtab = nullptr;
    unsigned *ktp = nullptr, *vtp = nullptr;
    cudaGetSymbolAddress((void**)&kvp, g_kv);
    cudaGetSymbolAddress((void**)&aop, g_ao);
    cudaGetSymbolAddress((void**)&wtab, g_wtab);
    cudaGetSymbolAddress((void**)&ktp, g_kt);
    cudaGetSymbolAddress((void**)&vtp, g_vt);

    const int attn_smem = (4 * TBUF + 128 * STR) * 4;   // 104448 B

    static bool attr_set = false;
    if (!attr_set) {
        cudaFuncSetAttribute(attn_tf32, cudaFuncAttributeMaxDynamicSharedMemorySize,
                             attn_smem);
        attr_set = true;
    }

    init_wtab<<<1, 64>>>(wtab);

    // 1) kv = x @ qkv_w[768:2304].T + qkv_b[768:2304]   (q slice unused)
    gemm_tf32<<<dim3(1536 / 128, MTOT / 64), 256>>>(
        x, qkv_w + (size_t)768 * 768, qkv_b + 768, kvp, MTOT, 1536, 768);

    // 2) repack to tf32: K [bh][tok][d] zero-padded, V^T [bh][d][tok]
    repack_kv<<<dim3(KPAD / 64, HEADS, NB), 256>>>(kvp, ktp, vtp);

    // 3) flash attention (cp.async double-buffered j-tiles)
    attn_tf32<<<dim3(KPAD / 128, HEADS, NB), 256, attn_smem>>>(
        ktp, vtp, wtab, aop);

    // 4) out = ao @ proj_w.T + proj_b
    gemm_tf32<<<dim3(768 / 128, MTOT / 64), 256>>>(
        aop, proj_w, proj_b, out, MTOT, 768, 768);
}

// round 10
// speedup vs baseline: 3.4372x; 1.0727x over previous
#include <cuda_runtime.h>
#include <math.h>

#define NTOK 1032
#define EMB  768
#define NB   8
#define HEADS 12
#define MTOT (NB * NTOK)   // 8256
#define KPAD 1152          // 18 j-tiles * 64 = 9 i-tiles * 128
#define NJT  18
#define NEGINF (-1e30f)
#define CEXP 0.18033688011112042f   // 0.125 * log2(e)

// Scratch (allocation-free)
__device__ float g_kv[(size_t)MTOT * 2 * EMB];             // [m][0:768)=k, [768:1536)=v
__device__ float g_ao[(size_t)MTOT * EMB];
__device__ unsigned g_kt[(size_t)NB * HEADS * KPAD * 64];  // tf32 K plain [bh][tok][d]
__device__ unsigned g_kf[(size_t)NB * HEADS * NJT * 4096]; // K fragment-major tiles
__device__ unsigned g_vf[(size_t)NB * HEADS * NJT * 4096]; // V^T fragment-major tiles
__device__ float g_btab[6272];   // [0,4225): exp(-.02(di^2+dl^2))*log2e ; rest zeros

__device__ __forceinline__ unsigned f2tf(float f) {
    unsigned r;
    asm("cvt.rna.tf32.f32 %0, %1;" : "=r"(r) : "f"(f));
    return r;
}
__device__ __forceinline__ float ex2(float x) {
    float r;
    asm("ex2.approx.f32 %0, %1;" : "=f"(r) : "f"(x));
    return r;
}
__device__ __forceinline__ void mma_tf32(float* c, const unsigned* a, unsigned b0, unsigned b1) {
    asm volatile(
        "mma.sync.aligned.m16n8k8.row.col.f32.tf32.tf32.f32 "
        "{%0,%1,%2,%3}, {%4,%5,%6,%7}, {%8,%9}, {%0,%1,%2,%3};"
        : "+f"(c[0]), "+f"(c[1]), "+f"(c[2]), "+f"(c[3])
        : "r"(a[0]), "r"(a[1]), "r"(a[2]), "r"(a[3]), "r"(b0), "r"(b1));
}
__device__ __forceinline__ void cp_async16(void* smem_dst, const void* gmem_src) {
    unsigned d = (unsigned)__cvta_generic_to_shared(smem_dst);
    asm volatile("cp.async.cg.shared.global [%0], [%1], 16;" :: "r"(d), "l"(gmem_src));
}
__device__ __forceinline__ void cp_commit() { asm volatile("cp.async.commit_group;"); }
__device__ __forceinline__ void cp_wait1()  { asm volatile("cp.async.wait_group 1;"); }

__global__ void init_btab(float* bt) {
    for (int i = threadIdx.x; i < 6272; i += 256) {
        float v = 0.0f;
        if (i < 4225) {
            int di = i / 65 - 32, dl = i % 65 - 32;
            v = __expf(-0.02f * (float)(di * di + dl * dl)) * 1.4426950408889634f;
        }
        bt[i] = v;
    }
}

// ---------------------------------------------------------------------------
// C[M,N] = A[M,K] @ W[N,K]^T + bias[N]   (tf32 tensor-core)
// ---------------------------------------------------------------------------
__global__ __launch_bounds__(256) void gemm_tf32(
    const float* __restrict__ A, const float* __restrict__ W,
    const float* __restrict__ bias, float* __restrict__ C,
    int M, int N, int K)
{
    __shared__ unsigned As[64][36];
    __shared__ unsigned Bs[128][36];

    const int tid = threadIdx.x;
    const int lane = tid & 31, wid = tid >> 5;
    const int g = lane >> 2, l = lane & 3;
    const int wm = (wid >> 2) * 32, wn = (wid & 3) * 32;
    const int m0 = blockIdx.y * 64, n0 = blockIdx.x * 128;

    float acc[2][4][4];
#pragma unroll
    for (int mt = 0; mt < 2; mt++)
#pragma unroll
        for (int nt = 0; nt < 4; nt++)
#pragma unroll
            for (int e = 0; e < 4; e++) acc[mt][nt][e] = 0.0f;

    const int NT = K / 32;
    const int rA0 = tid >> 3, qA0 = tid & 7;
    float4 ra[2], rb[4];

#define LOAD_TILE(KT)                                                          \
    {                                                                          \
        int kb = (KT) * 32;                                                    \
        _Pragma("unroll")                                                      \
        for (int i = 0; i < 2; i++)                                            \
            ra[i] = *(const float4*)(A + (size_t)(m0 + rA0 + i * 32) * K + kb + qA0 * 4); \
        _Pragma("unroll")                                                      \
        for (int i = 0; i < 4; i++)                                            \
            rb[i] = *(const float4*)(W + (size_t)(n0 + rA0 + i * 32) * K + kb + qA0 * 4); \
    }
#define STORE_TILE()                                                           \
    {                                                                          \
        _Pragma("unroll")                                                      \
        for (int i = 0; i < 2; i++) {                                          \
            unsigned* p = &As[rA0 + i * 32][qA0 * 4];                          \
            p[0] = f2tf(ra[i].x); p[1] = f2tf(ra[i].y);                        \
            p[2] = f2tf(ra[i].z); p[3] = f2tf(ra[i].w);                        \
        }                                                                      \
        _Pragma("unroll")                                                      \
        for (int i = 0; i < 4; i++) {                                          \
            unsigned* p = &Bs[rA0 + i * 32][qA0 * 4];                          \
            p[0] = f2tf(rb[i].x); p[1] = f2tf(rb[i].y);                        \
            p[2] = f2tf(rb[i].z); p[3] = f2tf(rb[i].w);                        \
        }                                                                      \
    }

    LOAD_TILE(0);
    STORE_TILE();
    __syncthreads();

    for (int kt = 0; kt < NT; kt++) {
        const bool more = (kt + 1) < NT;
        if (more) LOAD_TILE(kt + 1);

#pragma unroll
        for (int ks = 0; ks < 4; ks++) {
            int k0 = ks * 8;
            unsigned af[2][4], bf[4][2];
#pragma unroll
            for (int mt = 0; mt < 2; mt++) {
                int rr = wm + mt * 16 + g;
                af[mt][0] = As[rr][k0 + l];
                af[mt][1] = As[rr + 8][k0 + l];
                af[mt][2] = As[rr][k0 + 4 + l];
                af[mt][3] = As[rr + 8][k0 + 4 + l];
            }
#pragma unroll
            for (int nt = 0; nt < 4; nt++) {
                int cc = wn + nt * 8 + g;
                bf[nt][0] = Bs[cc][k0 + l];
                bf[nt][1] = Bs[cc][k0 + 4 + l];
            }
#pragma unroll
            for (int mt = 0; mt < 2; mt++)
#pragma unroll
                for (int nt = 0; nt < 4; nt++)
                    mma_tf32(acc[mt][nt], af[mt], bf[nt][0], bf[nt][1]);
        }
        __syncthreads();
        if (more) { STORE_TILE(); __syncthreads(); }
    }

#pragma unroll
    for (int mt = 0; mt < 2; mt++) {
#pragma unroll
        for (int nt = 0; nt < 4; nt++) {
            int row = m0 + wm + mt * 16 + g;
            int col = n0 + wn + nt * 8 + (l << 1);
            float b0 = bias[col], b1 = bias[col + 1];
            *(float2*)&C[(size_t)row * N + col] =
                make_float2(acc[mt][nt][0] + b0, acc[mt][nt][1] + b1);
            *(float2*)&C[(size_t)(row + 8) * N + col] =
                make_float2(acc[mt][nt][2] + b0, acc[mt][nt][3] + b1);
        }
    }
#undef LOAD_TILE
#undef STORE_TILE
}

// ---------------------------------------------------------------------------
// Repack: kv (f32) ->
//   Kt plain tf32 [bh][KPAD][64]  (for A-fragment hoist, zero-padded rows)
//   Kf fragment-major tiles: per (bh, jt): 8 nt x 32 lane x 16 words, where
//     lane (g,l) word (4q+t) = K[nt*8+g][(2q + (t>>1))*8 + (t&1)*4 + l]
//   Vf same packing of V^T: lane (g,l) word (4q+t) = V[(2q+(t>>1))*8+(t&1)*4+l][nt*8+g]
// ---------------------------------------------------------------------------
__global__ __launch_bounds__(256) void repack_kv(
    const float* __restrict__ kv, unsigned* __restrict__ Kt,
    unsigned* __restrict__ Kf, unsigned* __restrict__ Vf)
{
    __shared__ float sk[64][65];
    __shared__ float sv[64][65];
    const int tid = threadIdx.x;
    const int jt = blockIdx.x, h = blockIdx.y, b = blockIdx.z;
    const int j0 = jt * 64, bh = b * HEADS + h;

    const float* Kb = kv + (size_t)b * NTOK * (2 * EMB) + h * 64;
    const float* Vb = Kb + EMB;

#pragma unroll
    for (int i = 0; i < 4; i++) {
        int id = tid + i * 256;
        int r = id >> 4, q = (id & 15) << 2;   // row 0..63, col 0,4,..60
        int gj = j0 + r;
        float4 kk = make_float4(0.f, 0.f, 0.f, 0.f), vv = kk;
        if (gj < NTOK) {
            kk = *(const float4*)(Kb + (size_t)gj * (2 * EMB) + q);
            vv = *(const float4*)(Vb + (size_t)gj * (2 * EMB) + q);
        }
        uint4 ko = make_uint4(f2tf(kk.x), f2tf(kk.y), f2tf(kk.z), f2tf(kk.w));
        *(uint4*)&Kt[((size_t)bh * KPAD + j0 + r) * 64 + q] = ko;
        sk[r][q] = kk.x; sk[r][q + 1] = kk.y; sk[r][q + 2] = kk.z; sk[r][q + 3] = kk.w;
        sv[r][q] = vv.x; sv[r][q + 1] = vv.y; sv[r][q + 2] = vv.z; sv[r][q + 3] = vv.w;
    }
    __syncthreads();

    // fragment-major write: thread = (nt, lane)
    const int nt = tid >> 5, lane = tid & 31;
    const int g = lane >> 2, l = lane & 3;
    const int row = nt * 8 + g;
    const size_t fb = ((size_t)bh * NJT + jt) * 4096;
#pragma unroll
    for (int q = 0; q < 4; q++) {
        int c0 = 16 * q + l;
        uint4 kw = make_uint4(f2tf(sk[row][c0]),     f2tf(sk[row][c0 + 4]),
                              f2tf(sk[row][c0 + 8]), f2tf(sk[row][c0 + 12]));
        uint4 vw = make_uint4(f2tf(sv[c0][row]),     f2tf(sv[c0 + 4][row]),
                              f2tf(sv[c0 + 8][row]), f2tf(sv[c0 + 12][row]));
        size_t off = fb + ((size_t)(nt * 32 + lane) * 4 + q) * 4;
        *(uint4*)&Kf[off] = kw;
        *(uint4*)&Vf[off] = vw;
    }
}

// ---------------------------------------------------------------------------
// Flash attention, tf32 MMA. Block = 256 thr (8 warps), i-tile 128, j-tile 64.
// Fragment-major smem tiles, 20-word lane stride (bank-conflict-free LDS.128).
// No running max (scores bounded); softmax = 1 FFMA + 1 EX2 per element with
// log2e-folded bias table. Tiles specialized: FIRST (nt0 bias=0), MID, LAST
// (nt>=1 fully masked -> skipped).
// smem: sK[2][5120] + sV[2][5120] + sP[128*68]  = 116736 B
// ---------------------------------------------------------------------------
#define FTBUF 5120
#define STR 68

extern __shared__ unsigned smem_dyn[];

__global__ __launch_bounds__(256) void attn_tf32(
    const unsigned* __restrict__ Kt, const unsigned* __restrict__ Kf,
    const unsigned* __restrict__ Vf, const float* __restrict__ btab,
    float* __restrict__ out)
{
    unsigned* sK = smem_dyn;                   // 2 * FTBUF
    unsigned* sV = smem_dyn + 2 * FTBUF;       // 2 * FTBUF
    unsigned* sP = smem_dyn + 4 * FTBUF;       // 128 * STR

    const int tid = threadIdx.x, lane = tid & 31, w = tid >> 5;
    const int g = lane >> 2, l = lane & 3, l2 = l << 1;
    const int i0 = blockIdx.x * 128, h = blockIdx.y, b = blockIdx.z;
    const int bh = b * HEADS + h;

    const unsigned* Ktb = Kt + (size_t)bh * KPAD * 64;
    const unsigned* Kfb = Kf + (size_t)bh * NJT * 4096;
    const unsigned* Vfb = Vf + (size_t)bh * NJT * 4096;

    auto stage = [&](int jts, int bufs) {
        const unsigned* gK = Kfb + (size_t)jts * 4096;
        const unsigned* gV = Vfb + (size_t)jts * 4096;
        unsigned* dK = sK + bufs * FTBUF;
        unsigned* dV = sV + bufs * FTBUF;
#pragma unroll
        for (int i = 0; i < 4; i++) {
            int cc = tid + i * 256;
            int sw = (cc >> 2) * 20 + (cc & 3) * 4;
            cp_async16(&dK[sw], &gK[cc * 4]);
            cp_async16(&dV[sw], &gV[cc * 4]);
        }
    };

    // ---- hoist Ki A-fragments from plain Kt (padded -> no bounds checks) ----
    const int r0 = i0 + w * 16 + g;
    unsigned ka[8][4];
#pragma unroll
    for (int ks = 0; ks < 8; ks++) {
        int k0 = ks * 8;
        ka[ks][0] = Ktb[(size_t)r0 * 64 + k0 + l];
        ka[ks][1] = Ktb[(size_t)(r0 + 8) * 64 + k0 + l];
        ka[ks][2] = Ktb[(size_t)r0 * 64 + k0 + 4 + l];
        ka[ks][3] = Ktb[(size_t)(r0 + 8) * 64 + k0 + 4 + l];
    }

    float oacc[8][4];
#pragma unroll
    for (int nt = 0; nt < 8; nt++)
#pragma unroll
        for (int e = 0; e < 4; e++) oacc[nt][e] = 0.0f;
    float l0r = 0.0f, l1r = 0.0f;

    const int gi0 = r0, gi1 = r0 + 8;
    // bias row bases: valid rows -> (phi+32)*65 + (plo+32); prefix rows -> zero tail
    const int rb0 = (gi0 >= 8) ? ((((gi0 - 8) >> 5) + 32) * 65 + ((gi0 - 8) & 31) + 32) : 6271;
    const int rb1 = (gi1 >= 8) ? ((((gi1 - 8) >> 5) + 32) * 65 + ((gi1 - 8) & 31) + 32) : 6271;
    const int prow = w * 16 + g;

    // prologue: stage tile 0
    stage(0, 0);
    cp_commit();

// 4-nt MMA group: load 16 uint4 B-fragments, issue 32 MMAs interleaved (dep dist 4)
#define SGRP(SB, ACC, N0G)                                                     \
    {                                                                          \
        uint4 fr[4][4];                                                        \
        _Pragma("unroll")                                                      \
        for (int t = 0; t < 4; t++) {                                          \
            const uint4* bp = (const uint4*)((SB) + (((N0G) + t) * 32 + lane) * 20); \
            fr[t][0] = bp[0]; fr[t][1] = bp[1]; fr[t][2] = bp[2]; fr[t][3] = bp[3]; \
        }                                                                      \
        _Pragma("unroll")                                                      \
        for (int ks = 0; ks < 8; ks++) {                                       \
            const int q = ks >> 1; const int od = ks & 1;                      \
            _Pragma("unroll")                                                  \
            for (int t = 0; t < 4; t++)                                        \
                mma_tf32(ACC[(N0G) + t], ka2[ks],                              \
                         od ? fr[t][q].z : fr[t][q].x,                         \
                         od ? fr[t][q].w : fr[t][q].y);                        \
        }                                                                      \
    }

// softmax for one nt. WB: 0 = no bias (FIRST nt0), 1 = bias
#define SMAXNT(NT, WB)                                                         \
    {                                                                          \
        float b00, b01, b10, b11;                                              \
        if (WB) {                                                              \
            int u0 = j0 + (NT) * 8 + l2 - 8;                                   \
            int t0i = (u0 >> 5) * 65 + (u0 & 31);                              \
            int u1 = u0 + 1;                                                   \
            int t1i = (u1 >> 5) * 65 + (u1 & 31);                              \
            b00 = __ldg(&btab[rb0 - t0i]); b01 = __ldg(&btab[rb0 - t1i]);      \
            b10 = __ldg(&btab[rb1 - t0i]); b11 = __ldg(&btab[rb1 - t1i]);      \
        } else { b00 = b01 = b10 = b11 = 0.0f; }                               \
        float p00 = ex2(fmaf(sacc[NT][0], CEXP, b00));                         \
        float p01 = ex2(fmaf(sacc[NT][1], CEXP, b01));                         \
        float p10 = ex2(fmaf(sacc[NT][2], CEXP, b10));                         \
        float p11 = ex2(fmaf(sacc[NT][3], CEXP, b11));                         \
        s0 += p00 + p01; s1 += p10 + p11;                                      \
        *(uint2*)&sP[prow * STR + (NT) * 8 + l2] = make_uint2(f2tf(p00), f2tf(p01)); \
        *(uint2*)&sP[(prow + 8) * STR + (NT) * 8 + l2] = make_uint2(f2tf(p10), f2tf(p11)); \
    }

// one tile. MODE: 0 = FIRST (jt 0), 1 = MID, 2 = LAST (jt 16)
#define TILE(JT, MODE)                                                         \
    {                                                                          \
        const int jt = (JT);                                                   \
        const int buf = jt & 1;                                                \
        if (jt < 16) stage(jt + 1, buf ^ 1);                                   \
        cp_commit();                                                           \
        cp_wait1();                                                            \
        __syncthreads();                                                       \
        const unsigned* sKb = sK + buf * FTBUF;                                \
        const unsigned* sVb = sV + buf * FTBUF;                                \
        const int j0 = jt * 64;                                                \
        const unsigned (*ka2)[4] = ka;                                         \
        float sacc[8][4];                                                      \
        _Pragma("unroll")                                                      \
        for (int nt = 0; nt < 8; nt++) {                                       \
            sacc[nt][0] = 0.f; sacc[nt][1] = 0.f;                              \
            sacc[nt][2] = 0.f; sacc[nt][3] = 0.f;                              \
        }                                                                      \
        SGRP(sKb, sacc, 0);                                                    \
        if (MODE != 2) SGRP(sKb, sacc, 4);                                     \
        float s0 = 0.0f, s1 = 0.0f;                                            \
        if (MODE == 2) {                                                       \
            SMAXNT(0, 1);                                                      \
            uint2 z2 = make_uint2(0u, 0u);                                     \
            _Pragma("unroll")                                                  \
            for (int nt = 1; nt < 8; nt++) {                                   \
                *(uint2*)&sP[prow * STR + nt * 8 + l2] = z2;                   \
                *(uint2*)&sP[(prow + 8) * STR + nt * 8 + l2] = z2;             \
            }                                                                  \
        } else {                                                               \
            SMAXNT(0, (MODE != 0));                                            \
            SMAXNT(1, 1); SMAXNT(2, 1); SMAXNT(3, 1);                          \
            SMAXNT(4, 1); SMAXNT(5, 1); SMAXNT(6, 1); SMAXNT(7, 1);            \
        }                                                                      \
        s0 += __shfl_xor_sync(0xffffffffu, s0, 1);                             \
        s0 += __shfl_xor_sync(0xffffffffu, s0, 2);                             \
        s1 += __shfl_xor_sync(0xffffffffu, s1, 1);                             \
        s1 += __shfl_xor_sync(0xffffffffu, s1, 2);                             \
        l0r += s0; l1r += s1;                                                  \
        __syncwarp();                                                          \
        unsigned paf[8][4];                                                    \
        _Pragma("unroll")                                                      \
        for (int ks = 0; ks < 8; ks++) {                                       \
            int k0 = ks * 8;                                                   \
            paf[ks][0] = sP[prow * STR + k0 + l];                              \
            paf[ks][1] = sP[(prow + 8) * STR + k0 + l];                        \
            paf[ks][2] = sP[prow * STR + k0 + 4 + l];                          \
            paf[ks][3] = sP[(prow + 8) * STR + k0 + 4 + l];                    \
        }                                                                      \
        {                                                                      \
            const unsigned (*ka2)[4] = paf;                                    \
            SGRP(sVb, oacc, 0);                                                \
            SGRP(sVb, oacc, 4);                                                \
        }                                                                      \
        __syncthreads();                                                       \
    }

    TILE(0, 0);
#pragma unroll 1
    for (int jtm = 1; jtm < 16; jtm++) TILE(jtm, 1);
    TILE(16, 2);

    // ---- epilogue ----
    float inv0 = 1.0f / l0r, inv1 = 1.0f / l1r;
#pragma unroll
    for (int nt = 0; nt < 8; nt++) {
        int d = h * 64 + nt * 8 + l2;
        if (gi0 < NTOK)
            *(float2*)&out[((size_t)b * NTOK + gi0) * EMB + d] =
                make_float2(oacc[nt][0] * inv0, oacc[nt][1] * inv0);
        if (gi1 < NTOK)
            *(float2*)&out[((size_t)b * NTOK + gi1) * EMB + d] =
                make_float2(oacc[nt][2] * inv1, oacc[nt][3] * inv1);
    }
}

// ---------------------------------------------------------------------------
extern "C" void kernel_launch(void* const* d_in, const int* in_sizes, int n_in,
                              void* d_out, int out_size)
{
    const float* x      = (const float*)d_in[0];
    const float* qkv_w  = (const float*)d_in[1];  // [2304, 768]
    const float* qkv_b  = (const float*)d_in[2];  // [2304]
    const float* proj_w = (const float*)d_in[3];  // [768, 768]
    const float* proj_b = (const float*)d_in[4];  // [768]
    float* out = (float*)d_out;

    float *kvp = nullptr, *aop = nullptr, *btp = nullptr;
    unsigned *ktp = nullptr, *kfp = nullptr, *vfp = nullptr;
    cudaGetSymbolAddress((void**)&kvp, g_kv);
    cudaGetSymbolAddress((void**)&aop, g_ao);
    cudaGetSymbolAddress((void**)&btp, g_btab);
    cudaGetSymbolAddress((void**)&ktp, g_kt);
    cudaGetSymbolAddress((void**)&kfp, g_kf);
    cudaGetSymbolAddress((void**)&vfp, g_vf);

    const int attn_smem = (4 * FTBUF + 128 * STR) * 4;   // 116736 B

    static bool attr_set = false;
    if (!attr_set) {
        cudaFuncSetAttribute(attn_tf32, cudaFuncAttributeMaxDynamicSharedMemorySize,
                             attn_smem);
        attr_set = true;
    }

    init_btab<<<1, 256>>>(btp);

    // 1) kv = x @ qkv_w[768:2304].T + qkv_b[768:2304]   (q slice unused)
    gemm_tf32<<<dim3(1536 / 128, MTOT / 64), 256>>>(
        x, qkv_w + (size_t)768 * 768, qkv_b + 768, kvp, MTOT, 1536, 768);

    // 2) repack: plain Kt + fragment-major Kf/Vf tiles
    repack_kv<<<dim3(NJT, HEADS, NB), 256>>>(kvp, ktp, kfp, vfp);

    // 3) flash attention
    attn_tf32<<<dim3(KPAD / 128, HEADS, NB), 256, attn_smem>>>(
        ktp, kfp, vfp, btp, aop);

    // 4) out = ao @ proj_w.T + proj_b
    gemm_tf32<<<dim3(768 / 128, MTOT / 64), 256>>>(
        aop, proj_w, proj_b, out, MTOT, 768, 768);
}